// round 6
// baseline (speedup 1.0000x reference)
#include <cuda_runtime.h>
#include <cuda_bf16.h>
#include <cstdint>

#define B_ROWS 16384
#define IN_DIM 64
#define OUT_DIM 4096
#define BM 128
#define BN 128

// ---- device-global scratch (alloc-guard-safe) ----
__device__ __nv_bfloat16 g_xhi[B_ROWS * IN_DIM];
__device__ __nv_bfloat16 g_xlo[B_ROWS * IN_DIM];
__device__ __nv_bfloat16 g_chi[OUT_DIM * IN_DIM];
__device__ __nv_bfloat16 g_clo[OUT_DIM * IN_DIM];
__device__ float g_xn[B_ROWS];
__device__ float g_cn[OUT_DIM];
__device__ float g_iv[OUT_DIM];

// ---- smem layout (bytes). Stage buffer overlays the (dead) tile region. ----
#define SA_HI 0
#define SA_LO 16384
#define SB_HI 32768
#define SB_LO 49152
#define S_STAGE 0                      // 128*132*4 = 67584, overlays tiles
#define S_XN  67584
#define S_CN  68096
#define S_IV  68608
#define SMEM_TOTAL 69120
#define STG_LD 132                     // stage row stride in floats

__device__ __forceinline__ uint32_t s2u(const void* p) {
    uint32_t a;
    asm("{ .reg .u64 t; cvta.to.shared.u64 t, %1; cvt.u32.u64 %0, t; }" : "=r"(a) : "l"(p));
    return a;
}

__device__ __forceinline__ void ldm_x4(uint32_t* r, uint32_t addr) {
    asm volatile("ldmatrix.sync.aligned.m8n8.x4.shared.b16 {%0,%1,%2,%3}, [%4];"
                 : "=r"(r[0]), "=r"(r[1]), "=r"(r[2]), "=r"(r[3]) : "r"(addr));
}

__device__ __forceinline__ void mma16816(float* c, const uint32_t* a,
                                         uint32_t b0, uint32_t b1) {
    asm volatile(
        "mma.sync.aligned.m16n8k16.row.col.f32.bf16.bf16.f32 "
        "{%0,%1,%2,%3}, {%4,%5,%6,%7}, {%8,%9}, {%0,%1,%2,%3};"
        : "+f"(c[0]), "+f"(c[1]), "+f"(c[2]), "+f"(c[3])
        : "r"(a[0]), "r"(a[1]), "r"(a[2]), "r"(a[3]), "r"(b0), "r"(b1));
}

// ---- prep (fused): split f32 -> bf16 hi/lo, row norms, inv_sigma2 ----
__global__ void prep_all(const float* __restrict__ x, const float* __restrict__ c,
                         const float* __restrict__ ls) {
    int gw = (blockIdx.x * blockDim.x + threadIdx.x) >> 5;
    int lane = threadIdx.x & 31;
    const float* src;
    __nv_bfloat162 *dhi, *dlo;
    int row;
    if (gw < B_ROWS) {
        row = gw; src = x;
        dhi = (__nv_bfloat162*)g_xhi; dlo = (__nv_bfloat162*)g_xlo;
    } else {
        row = gw - B_ROWS;
        if (row >= OUT_DIM) return;
        src = c;
        dhi = (__nv_bfloat162*)g_chi; dlo = (__nv_bfloat162*)g_clo;
    }
    float2 v = ((const float2*)src)[row * 32 + lane];
    __nv_bfloat16 h0 = __float2bfloat16_rn(v.x);
    __nv_bfloat16 h1 = __float2bfloat16_rn(v.y);
    __nv_bfloat16 l0 = __float2bfloat16_rn(v.x - __bfloat162float(h0));
    __nv_bfloat16 l1 = __float2bfloat16_rn(v.y - __bfloat162float(h1));
    __nv_bfloat162 hp; hp.x = h0; hp.y = h1;
    __nv_bfloat162 lp; lp.x = l0; lp.y = l1;
    dhi[row * 32 + lane] = hp;
    dlo[row * 32 + lane] = lp;
    float s = v.x * v.x + v.y * v.y;
#pragma unroll
    for (int o = 16; o; o >>= 1) s += __shfl_xor_sync(0xffffffffu, s, o);
    if (lane == 0) {
        if (gw < B_ROWS) g_xn[row] = s;
        else { g_cn[row] = s; g_iv[row] = __expf(-2.0f * ls[row]); }
    }
}

// ---- main: 128x128 tile, 256 thr, 2 CTA/SM, split-bf16 mma.sync ----
__global__ void __launch_bounds__(256, 2)
rbf_mma(float* __restrict__ out) {
    extern __shared__ char smem[];
    const uint32_t sb = s2u(smem);
    const int tid = threadIdx.x;
    const int bn = blockIdx.x * BN;
    const int bm = blockIdx.y * BM;

    // ---- global -> smem, XOR-swizzled (16B chunk q -> q ^ (row&7)) ----
    {
        const uint4* axh = (const uint4*)(g_xhi + (size_t)bm * IN_DIM);
        const uint4* axl = (const uint4*)(g_xlo + (size_t)bm * IN_DIM);
        const uint4* bch = (const uint4*)(g_chi + (size_t)bn * IN_DIM);
        const uint4* bcl = (const uint4*)(g_clo + (size_t)bn * IN_DIM);
#pragma unroll
        for (int l = tid; l < 1024; l += 256) {
            int row = l >> 3, q = l & 7;
            int off = row * 128 + ((q ^ (row & 7)) << 4);
            *(uint4*)(smem + SA_HI + off) = axh[l];
            *(uint4*)(smem + SA_LO + off) = axl[l];
            *(uint4*)(smem + SB_HI + off) = bch[l];
            *(uint4*)(smem + SB_LO + off) = bcl[l];
        }
        if (tid < 128) {
            ((float*)(smem + S_XN))[tid] = g_xn[bm + tid];
            ((float*)(smem + S_CN))[tid] = g_cn[bn + tid];
            ((float*)(smem + S_IV))[tid] = g_iv[bn + tid];
        }
    }
    __syncthreads();

    const int wid = tid >> 5, lane = tid & 31;
    const int wm = wid >> 2, wn = wid & 3;   // 2x4 warp grid, 64x32 warp tiles

    const int lrow = lane & 15;
    const int ksel = lane >> 4;              // lanes 16-31 take the odd 16B chunk

    uint32_t aBase[4], bBase[2];
    int aSz[4], bSz[2];
#pragma unroll
    for (int t = 0; t < 4; t++) {
        int ra = wm * 64 + t * 16 + lrow;
        aBase[t] = sb + SA_HI + ra * 128;
        aSz[t] = ra & 7;
    }
#pragma unroll
    for (int t = 0; t < 2; t++) {
        int rb = wn * 32 + t * 16 + lrow;
        bBase[t] = sb + SB_HI + rb * 128;
        bSz[t] = rb & 7;
    }

    float acc[4][4][4];
#pragma unroll
    for (int i = 0; i < 4; i++)
#pragma unroll
        for (int j = 0; j < 4; j++)
#pragma unroll
            for (int k = 0; k < 4; k++) acc[i][j][k] = 0.f;

#pragma unroll
    for (int ks = 0; ks < 4; ks++) {
        const int kc = ks * 2 + ksel;        // 16B-chunk index along K
        uint32_t Ah[4][4], Bh[2][4];
#pragma unroll
        for (int t = 0; t < 4; t++) ldm_x4(Ah[t], aBase[t] + ((uint32_t)(kc ^ aSz[t]) << 4));
#pragma unroll
        for (int t = 0; t < 2; t++) ldm_x4(Bh[t], bBase[t] + ((uint32_t)(kc ^ bSz[t]) << 4));
        // hi*hi
#pragma unroll
        for (int mt = 0; mt < 4; mt++)
#pragma unroll
            for (int p = 0; p < 2; p++) {
                mma16816(acc[mt][p * 2 + 0], Ah[mt], Bh[p][0], Bh[p][2]);
                mma16816(acc[mt][p * 2 + 1], Ah[mt], Bh[p][1], Bh[p][3]);
            }
        // hi*lo
        {
            uint32_t Bl[2][4];
#pragma unroll
            for (int t = 0; t < 2; t++)
                ldm_x4(Bl[t], bBase[t] + 16384 + ((uint32_t)(kc ^ bSz[t]) << 4));
#pragma unroll
            for (int mt = 0; mt < 4; mt++)
#pragma unroll
                for (int p = 0; p < 2; p++) {
                    mma16816(acc[mt][p * 2 + 0], Ah[mt], Bl[p][0], Bl[p][2]);
                    mma16816(acc[mt][p * 2 + 1], Ah[mt], Bl[p][1], Bl[p][3]);
                }
        }
        // lo*hi
        {
            uint32_t Al[4][4];
#pragma unroll
            for (int t = 0; t < 4; t++)
                ldm_x4(Al[t], aBase[t] + 16384 + ((uint32_t)(kc ^ aSz[t]) << 4));
#pragma unroll
            for (int mt = 0; mt < 4; mt++)
#pragma unroll
                for (int p = 0; p < 2; p++) {
                    mma16816(acc[mt][p * 2 + 0], Al[mt], Bh[p][0], Bh[p][2]);
                    mma16816(acc[mt][p * 2 + 1], Al[mt], Bh[p][1], Bh[p][3]);
                }
        }
    }

    // ---- epilogue: exp2(min((2d - xn - cn)*ivl, 0)) -> smem stage ----
    const float* xn_s = (const float*)(smem + S_XN);
    const float* cn_s = (const float*)(smem + S_CN);
    const float* iv_s = (const float*)(smem + S_IV);
    const int qr = lane >> 2;          // 0..7
    const int qc = (lane & 3) * 2;     // 0,2,4,6
    const float L2E = 1.4426950408889634f;

    // hoist per-column constants (8 cols per lane)
    float cn_l[8], ivl_l[8];
#pragma unroll
    for (int nt = 0; nt < 4; nt++) {
        int col = wn * 32 + nt * 8 + qc;
        cn_l[nt * 2 + 0] = cn_s[col];
        cn_l[nt * 2 + 1] = cn_s[col + 1];
        ivl_l[nt * 2 + 0] = iv_s[col] * L2E;
        ivl_l[nt * 2 + 1] = iv_s[col + 1] * L2E;
    }
    // per-row xn (8 rows per lane)
    float xn_l[8];
#pragma unroll
    for (int mt = 0; mt < 4; mt++) {
        xn_l[mt * 2 + 0] = xn_s[wm * 64 + mt * 16 + qr];
        xn_l[mt * 2 + 1] = xn_s[wm * 64 + mt * 16 + qr + 8];
    }

    __syncthreads();   // tile smem now dead; safe to overlay stage
    float* stage = (float*)(smem + S_STAGE);

#pragma unroll
    for (int mt = 0; mt < 4; mt++) {
        int r0 = wm * 64 + mt * 16 + qr;
        float xn0 = xn_l[mt * 2 + 0], xn1 = xn_l[mt * 2 + 1];
#pragma unroll
        for (int nt = 0; nt < 4; nt++) {
            int col = wn * 32 + nt * 8 + qc;
            float cn0 = cn_l[nt * 2], cn1 = cn_l[nt * 2 + 1];
            float iv0 = ivl_l[nt * 2], iv1 = ivl_l[nt * 2 + 1];
            const float* a = acc[mt][nt];
            float2 v0, v1;
            v0.x = exp2f(fminf(fmaf(2.f, a[0], -(xn0 + cn0)) * iv0, 0.f));
            v0.y = exp2f(fminf(fmaf(2.f, a[1], -(xn0 + cn1)) * iv1, 0.f));
            v1.x = exp2f(fminf(fmaf(2.f, a[2], -(xn1 + cn0)) * iv0, 0.f));
            v1.y = exp2f(fminf(fmaf(2.f, a[3], -(xn1 + cn1)) * iv1, 0.f));
            *(float2*)(stage + r0 * STG_LD + col) = v0;
            *(float2*)(stage + (r0 + 8) * STG_LD + col) = v1;
        }
    }
    __syncthreads();

    // ---- coalesced writeout: 16 rows per warp, LDS.128 + STG.128 ----
#pragma unroll
    for (int i = 0; i < 16; i++) {
        int row = wid * 16 + i;
        float4 v = *(float4*)(stage + row * STG_LD + lane * 4);
        *(float4*)(out + (size_t)(bm + row) * OUT_DIM + bn + lane * 4) = v;
    }
}

extern "C" void kernel_launch(void* const* d_in, const int* in_sizes, int n_in,
                              void* d_out, int out_size) {
    const float* x  = (const float*)d_in[0];
    const float* c  = (const float*)d_in[1];
    const float* ls = (const float*)d_in[2];
    float* out = (float*)d_out;
    (void)in_sizes; (void)n_in; (void)out_size;

    cudaFuncSetAttribute(rbf_mma, cudaFuncAttributeMaxDynamicSharedMemorySize, SMEM_TOTAL);

    prep_all<<<(B_ROWS + OUT_DIM) / 8, 256>>>(x, c, ls);

    dim3 grid(OUT_DIM / BN, B_ROWS / BM);
    rbf_mma<<<grid, 256, SMEM_TOTAL>>>(out);
}

// round 8
// speedup vs baseline: 1.1357x; 1.1357x over previous
#include <cuda_runtime.h>
#include <cuda_bf16.h>
#include <cstdint>

#define B_ROWS 16384
#define IN_DIM 64
#define OUT_DIM 4096
#define BM 128
#define BN 128
#define NTILE_N (OUT_DIM / BN)          // 32
#define NUNITS ((B_ROWS / BM) * NTILE_N) // 4096
#define NCTA 304                         // 2 per SM (152 SMs on GB300)

// ---- device-global scratch (alloc-guard-safe) ----
__device__ __nv_bfloat16 g_xhi[B_ROWS * IN_DIM];
__device__ __nv_bfloat16 g_xlo[B_ROWS * IN_DIM];
__device__ __nv_bfloat16 g_chi[OUT_DIM * IN_DIM];
__device__ __nv_bfloat16 g_clo[OUT_DIM * IN_DIM];
__device__ float g_xn[B_ROWS];
__device__ float g_cn[OUT_DIM];
__device__ float g_iv[OUT_DIM];

// ---- smem layout (bytes) ----
#define SA_HI 0                 // 16KB
#define SA_LO 16384             // 16KB
#define SB0   32768             // B buf0: hi 16K @ +0, lo 16K @ +16384
#define SB1   65536             // B buf1
#define S_XN  98304             // 128 f32
#define S_CN0 98816             // 128 f32
#define S_IV0 99328
#define S_CN1 99840
#define S_IV1 100352
#define SMEM_TOTAL 100864

__device__ __forceinline__ uint32_t s2u(const void* p) {
    uint32_t a;
    asm("{ .reg .u64 t; cvta.to.shared.u64 t, %1; cvt.u32.u64 %0, t; }" : "=r"(a) : "l"(p));
    return a;
}
__device__ __forceinline__ void cp16(uint32_t dst, const void* src) {
    asm volatile("cp.async.cg.shared.global [%0], [%1], 16;" :: "r"(dst), "l"(src));
}
#define CPCOMMIT() asm volatile("cp.async.commit_group;" ::: "memory")
#define CPWAIT(n)  asm volatile("cp.async.wait_group %0;" :: "n"(n) : "memory")

__device__ __forceinline__ void ldm_x4(uint32_t* r, uint32_t addr) {
    asm volatile("ldmatrix.sync.aligned.m8n8.x4.shared.b16 {%0,%1,%2,%3}, [%4];"
                 : "=r"(r[0]), "=r"(r[1]), "=r"(r[2]), "=r"(r[3]) : "r"(addr));
}
__device__ __forceinline__ void mma16816(float* c, const uint32_t* a,
                                         uint32_t b0, uint32_t b1) {
    asm volatile(
        "mma.sync.aligned.m16n8k16.row.col.f32.bf16.bf16.f32 "
        "{%0,%1,%2,%3}, {%4,%5,%6,%7}, {%8,%9}, {%0,%1,%2,%3};"
        : "+f"(c[0]), "+f"(c[1]), "+f"(c[2]), "+f"(c[3])
        : "r"(a[0]), "r"(a[1]), "r"(a[2]), "r"(a[3]), "r"(b0), "r"(b1));
}

// ---- prep (fused): split f32 -> bf16 hi/lo, row norms, inv_sigma2 ----
__global__ void prep_all(const float* __restrict__ x, const float* __restrict__ c,
                         const float* __restrict__ ls) {
    int gw = (blockIdx.x * blockDim.x + threadIdx.x) >> 5;
    int lane = threadIdx.x & 31;
    const float* src;
    __nv_bfloat162 *dhi, *dlo;
    int row;
    if (gw < B_ROWS) {
        row = gw; src = x;
        dhi = (__nv_bfloat162*)g_xhi; dlo = (__nv_bfloat162*)g_xlo;
    } else {
        row = gw - B_ROWS;
        if (row >= OUT_DIM) return;
        src = c;
        dhi = (__nv_bfloat162*)g_chi; dlo = (__nv_bfloat162*)g_clo;
    }
    float2 v = ((const float2*)src)[row * 32 + lane];
    __nv_bfloat16 h0 = __float2bfloat16_rn(v.x);
    __nv_bfloat16 h1 = __float2bfloat16_rn(v.y);
    __nv_bfloat16 l0 = __float2bfloat16_rn(v.x - __bfloat162float(h0));
    __nv_bfloat16 l1 = __float2bfloat16_rn(v.y - __bfloat162float(h1));
    __nv_bfloat162 hp; hp.x = h0; hp.y = h1;
    __nv_bfloat162 lp; lp.x = l0; lp.y = l1;
    dhi[row * 32 + lane] = hp;
    dlo[row * 32 + lane] = lp;
    float s = v.x * v.x + v.y * v.y;
#pragma unroll
    for (int o = 16; o; o >>= 1) s += __shfl_xor_sync(0xffffffffu, s, o);
    if (lane == 0) {
        if (gw < B_ROWS) g_xn[row] = s;
        else { g_cn[row] = s; g_iv[row] = __expf(-2.0f * ls[row]); }
    }
}

// issue cp.async for B tile (32KB hi+lo) + cn/iv aux into buffer `buf`
__device__ __forceinline__ void load_B(uint32_t sb, int unit, int buf, int tid) {
    const int bn = (unit & (NTILE_N - 1)) * BN;
    const uint32_t base = sb + (buf ? SB1 : SB0);
#pragma unroll
    for (int i = 0; i < 8; i++) {
        int l = tid + i * 256;           // 0..2047
        int half = l >> 10;              // 0=hi, 1=lo
        int li = l & 1023;
        int row = li >> 3, q = li & 7;
        uint32_t dst = base + half * 16384 + row * 128 + ((q ^ (row & 7)) << 4);
        const __nv_bfloat16* src = (half ? g_clo : g_chi) + (size_t)(bn + row) * IN_DIM + q * 8;
        cp16(dst, src);
    }
    if (tid < 32)
        cp16(sb + (buf ? S_CN1 : S_CN0) + tid * 16, g_cn + bn + tid * 4);
    else if (tid < 64)
        cp16(sb + (buf ? S_IV1 : S_IV0) + (tid - 32) * 16, g_iv + bn + (tid - 32) * 4);
}

// issue cp.async for A strip (32KB hi+lo) + xn
__device__ __forceinline__ void load_A(uint32_t sb, int bmi, int tid) {
    const int bm = bmi * BM;
#pragma unroll
    for (int i = 0; i < 8; i++) {
        int l = tid + i * 256;
        int half = l >> 10;
        int li = l & 1023;
        int row = li >> 3, q = li & 7;
        uint32_t dst = sb + (half ? SA_LO : SA_HI) + row * 128 + ((q ^ (row & 7)) << 4);
        const __nv_bfloat16* src = (half ? g_xlo : g_xhi) + (size_t)(bm + row) * IN_DIM + q * 8;
        cp16(dst, src);
    }
    if (tid < 32)
        cp16(sb + S_XN + tid * 16, g_xn + bm + tid * 4);
}

// ---- persistent main: A-resident strip, double-buffered B, split-bf16 mma ----
__global__ void __launch_bounds__(256, 2)
rbf_persist(float* __restrict__ out) {
    extern __shared__ char smem[];
    const uint32_t sb = s2u(smem);
    const int tid = threadIdx.x;
    const int cta = blockIdx.x;

    const int u0 = (cta * NUNITS) / NCTA;
    const int u1 = ((cta + 1) * NUNITS) / NCTA;

    int bmi = u0 >> 5;                   // 32 n-tiles per m-strip

    // prologue: A + B0 (group0), B1 (group1, possibly empty)
    load_A(sb, bmi, tid);
    load_B(sb, u0, 0, tid);
    CPCOMMIT();
    if (u0 + 1 < u1) load_B(sb, u0 + 1, 1, tid);
    CPCOMMIT();

    const int wid = tid >> 5, lane = tid & 31;
    const int wm = wid >> 2, wn = wid & 3;   // 2x4 warp grid, 64x32 warp tiles
    const int lrow = lane & 15;
    const int ksel = lane >> 4;
    const int sz = lrow & 7;                 // swizzle key (same for A and B rows)
    const int qr = lane >> 2;
    const int qc = (lane & 3) * 2;
    const float L2E = 1.4426950408889634f;

    uint32_t aBase[4];
#pragma unroll
    for (int t = 0; t < 4; t++)
        aBase[t] = sb + SA_HI + (wm * 64 + t * 16 + lrow) * 128;

    for (int t = u0; t < u1; ++t) {
        const int buf = (t - u0) & 1;
        CPWAIT(1);
        const int nbm = t >> 5;
        if (nbm != bmi) {                 // rare: new A strip
            __syncthreads();
            load_A(sb, nbm, tid);
            CPCOMMIT();
            CPWAIT(0);
            bmi = nbm;
        }
        __syncthreads();                  // B[buf] + A visible to all

        uint32_t bBase[2];
#pragma unroll
        for (int tt = 0; tt < 2; tt++)
            bBase[tt] = sb + (buf ? SB1 : SB0) + (wn * 32 + tt * 16 + lrow) * 128;

        float acc[4][4][4];
#pragma unroll
        for (int i = 0; i < 4; i++)
#pragma unroll
            for (int j = 0; j < 4; j++)
#pragma unroll
                for (int k = 0; k < 4; k++) acc[i][j][k] = 0.f;

#pragma unroll
        for (int ks = 0; ks < 4; ks++) {
            const int kc = ks * 2 + ksel;
            const uint32_t ko = (uint32_t)((kc ^ sz) << 4);
            uint32_t Ah[4][4], Bh[2][4];
#pragma unroll
            for (int tt = 0; tt < 4; tt++) ldm_x4(Ah[tt], aBase[tt] + ko);
#pragma unroll
            for (int tt = 0; tt < 2; tt++) ldm_x4(Bh[tt], bBase[tt] + ko);
            // hi*hi
#pragma unroll
            for (int mt = 0; mt < 4; mt++)
#pragma unroll
                for (int p = 0; p < 2; p++) {
                    mma16816(acc[mt][p * 2 + 0], Ah[mt], Bh[p][0], Bh[p][2]);
                    mma16816(acc[mt][p * 2 + 1], Ah[mt], Bh[p][1], Bh[p][3]);
                }
            // hi*lo
            {
                uint32_t Bl[2][4];
#pragma unroll
                for (int tt = 0; tt < 2; tt++) ldm_x4(Bl[tt], bBase[tt] + 16384 + ko);
#pragma unroll
                for (int mt = 0; mt < 4; mt++)
#pragma unroll
                    for (int p = 0; p < 2; p++) {
                        mma16816(acc[mt][p * 2 + 0], Ah[mt], Bl[p][0], Bl[p][2]);
                        mma16816(acc[mt][p * 2 + 1], Ah[mt], Bl[p][1], Bl[p][3]);
                    }
            }
            // lo*hi
            {
                uint32_t Al[4][4];
#pragma unroll
                for (int tt = 0; tt < 4; tt++) ldm_x4(Al[tt], aBase[tt] + 16384 + ko);
#pragma unroll
                for (int mt = 0; mt < 4; mt++)
#pragma unroll
                    for (int p = 0; p < 2; p++) {
                        mma16816(acc[mt][p * 2 + 0], Al[mt], Bh[p][0], Bh[p][2]);
                        mma16816(acc[mt][p * 2 + 1], Al[mt], Bh[p][1], Bh[p][3]);
                    }
            }
        }

        // epilogue constants (read BEFORE buffer is recycled)
        const float* xn_s = (const float*)(smem + S_XN);
        const float* cn_s = (const float*)(smem + (buf ? S_CN1 : S_CN0));
        const float* iv_s = (const float*)(smem + (buf ? S_IV1 : S_IV0));
        float cn_l[8], ivl_l[8], xn_l[8];
#pragma unroll
        for (int nt = 0; nt < 4; nt++) {
            int col = wn * 32 + nt * 8 + qc;
            cn_l[nt * 2 + 0] = cn_s[col];
            cn_l[nt * 2 + 1] = cn_s[col + 1];
            ivl_l[nt * 2 + 0] = iv_s[col] * L2E;
            ivl_l[nt * 2 + 1] = iv_s[col + 1] * L2E;
        }
#pragma unroll
        for (int mt = 0; mt < 4; mt++) {
            xn_l[mt * 2 + 0] = xn_s[wm * 64 + mt * 16 + qr];
            xn_l[mt * 2 + 1] = xn_s[wm * 64 + mt * 16 + qr + 8];
        }

        __syncthreads();                  // all ldmatrix done -> buf reusable
        if (t + 2 < u1) load_B(sb, t + 2, buf, tid);
        CPCOMMIT();                       // uniform group count (may be empty)

        // epilogue: out = exp2(min((2*dot - xn - cn) * iv*log2e, 0))
        const int bm = bmi * BM;
        const int bn = (t & (NTILE_N - 1)) * BN;
#pragma unroll
        for (int mt = 0; mt < 4; mt++) {
            int r0 = wm * 64 + mt * 16 + qr;
            float xn0 = xn_l[mt * 2 + 0], xn1 = xn_l[mt * 2 + 1];
#pragma unroll
            for (int nt = 0; nt < 4; nt++) {
                int col = wn * 32 + nt * 8 + qc;
                float cn0 = cn_l[nt * 2], cn1 = cn_l[nt * 2 + 1];
                float iv0 = ivl_l[nt * 2], iv1 = ivl_l[nt * 2 + 1];
                const float* a = acc[mt][nt];
                float2 v0, v1;
                v0.x = exp2f(fminf(fmaf(2.f, a[0], -(xn0 + cn0)) * iv0, 0.f));
                v0.y = exp2f(fminf(fmaf(2.f, a[1], -(xn0 + cn1)) * iv1, 0.f));
                v1.x = exp2f(fminf(fmaf(2.f, a[2], -(xn1 + cn0)) * iv0, 0.f));
                v1.y = exp2f(fminf(fmaf(2.f, a[3], -(xn1 + cn1)) * iv1, 0.f));
                *(float2*)(out + (size_t)(bm + r0) * OUT_DIM + bn + col) = v0;
                *(float2*)(out + (size_t)(bm + r0 + 8) * OUT_DIM + bn + col) = v1;
            }
        }
    }
}

extern "C" void kernel_launch(void* const* d_in, const int* in_sizes, int n_in,
                              void* d_out, int out_size) {
    const float* x  = (const float*)d_in[0];
    const float* c  = (const float*)d_in[1];
    const float* ls = (const float*)d_in[2];
    float* out = (float*)d_out;
    (void)in_sizes; (void)n_in; (void)out_size;

    cudaFuncSetAttribute(rbf_persist, cudaFuncAttributeMaxDynamicSharedMemorySize, SMEM_TOTAL);

    prep_all<<<(B_ROWS + OUT_DIM) / 8, 256>>>(x, c, ls);
    rbf_persist<<<NCTA, 256, SMEM_TOTAL>>>(out);
}

// round 9
// speedup vs baseline: 1.2133x; 1.0683x over previous
#include <cuda_runtime.h>
#include <cuda_bf16.h>
#include <cstdint>

#define B_ROWS 16384
#define IN_DIM 64
#define OUT_DIM 4096
#define BM 128
#define BN 128
#define NUNITS 4096        // (16384/128)*(4096/128)
#define NCTA 148
#define THREADS 320        // 8 consumer warps + 2 producer warps
#define NSTAGE 4

// ---- device-global scratch (alloc-guard-safe) ----
__device__ __nv_bfloat16 g_xhi[B_ROWS * IN_DIM];
__device__ __nv_bfloat16 g_xlo[B_ROWS * IN_DIM];
__device__ __nv_bfloat16 g_chi[OUT_DIM * IN_DIM];
__device__ __nv_bfloat16 g_clo[OUT_DIM * IN_DIM];
__device__ float g_xn[B_ROWS];
__device__ float g_cn[OUT_DIM];
__device__ float g_iv[OUT_DIM];

// ---- smem layout (bytes) ----
#define SA_HI   0            // A hi 16KB
#define SA_LO   16384        // A lo 16KB
#define ST_BASE 32768        // 4 stages
#define ST_SZ   33792        // per stage: Bhi 16K, Blo 16K, cn 512, iv 512, pad
#define ST_CN   32768        // offset within stage
#define ST_IV   33280
#define S_XN    167936       // 512B
#define BAR     168448       // mbarriers
#define SMEM_TOTAL 168960
// barriers: full[s]=BAR+8s, empty[s]=BAR+32+8s, a_full=BAR+64, a_empty=BAR+72

__device__ __forceinline__ uint32_t s2u(const void* p) {
    uint32_t a;
    asm("{ .reg .u64 t; cvta.to.shared.u64 t, %1; cvt.u32.u64 %0, t; }" : "=r"(a) : "l"(p));
    return a;
}
__device__ __forceinline__ void cp16(uint32_t dst, const void* src) {
    asm volatile("cp.async.cg.shared.global [%0], [%1], 16;" :: "r"(dst), "l"(src));
}
#define CPCOMMIT() asm volatile("cp.async.commit_group;" ::: "memory")
#define CPWAIT0()  asm volatile("cp.async.wait_group 0;" ::: "memory")

__device__ __forceinline__ void bar_init(uint32_t a, uint32_t cnt) {
    asm volatile("mbarrier.init.shared.b64 [%0], %1;" :: "r"(a), "r"(cnt) : "memory");
}
__device__ __forceinline__ void bar_arrive(uint32_t a) {
    uint64_t st;
    asm volatile("mbarrier.arrive.shared.b64 %0, [%1];" : "=l"(st) : "r"(a) : "memory");
}
__device__ __forceinline__ void bar_wait(uint32_t a, uint32_t parity) {
    uint32_t done;
    do {
        asm volatile(
            "{\n\t.reg .pred p;\n\t"
            "mbarrier.try_wait.parity.shared.b64 p, [%1], %2, 0x989680;\n\t"
            "selp.b32 %0, 1, 0, p;\n\t}"
            : "=r"(done) : "r"(a), "r"(parity) : "memory");
    } while (!done);
}
__device__ __forceinline__ void ldm_x4(uint32_t* r, uint32_t addr) {
    asm volatile("ldmatrix.sync.aligned.m8n8.x4.shared.b16 {%0,%1,%2,%3}, [%4];"
                 : "=r"(r[0]), "=r"(r[1]), "=r"(r[2]), "=r"(r[3]) : "r"(addr));
}
__device__ __forceinline__ void mma16816(float* c, const uint32_t* a,
                                         uint32_t b0, uint32_t b1) {
    asm volatile(
        "mma.sync.aligned.m16n8k16.row.col.f32.bf16.bf16.f32 "
        "{%0,%1,%2,%3}, {%4,%5,%6,%7}, {%8,%9}, {%0,%1,%2,%3};"
        : "+f"(c[0]), "+f"(c[1]), "+f"(c[2]), "+f"(c[3])
        : "r"(a[0]), "r"(a[1]), "r"(a[2]), "r"(a[3]), "r"(b0), "r"(b1));
}
__device__ __forceinline__ float ex2a(float x) {
    float r;
    asm("ex2.approx.f32 %0, %1;" : "=f"(r) : "f"(x));
    return r;
}

// ---- prep (fused): split f32 -> bf16 hi/lo, row norms, inv_sigma2 ----
__global__ void prep_all(const float* __restrict__ x, const float* __restrict__ c,
                         const float* __restrict__ ls) {
    int gw = (blockIdx.x * blockDim.x + threadIdx.x) >> 5;
    int lane = threadIdx.x & 31;
    const float* src;
    __nv_bfloat162 *dhi, *dlo;
    int row;
    if (gw < B_ROWS) {
        row = gw; src = x;
        dhi = (__nv_bfloat162*)g_xhi; dlo = (__nv_bfloat162*)g_xlo;
    } else {
        row = gw - B_ROWS;
        if (row >= OUT_DIM) return;
        src = c;
        dhi = (__nv_bfloat162*)g_chi; dlo = (__nv_bfloat162*)g_clo;
    }
    float2 v = ((const float2*)src)[row * 32 + lane];
    __nv_bfloat16 h0 = __float2bfloat16_rn(v.x);
    __nv_bfloat16 h1 = __float2bfloat16_rn(v.y);
    __nv_bfloat16 l0 = __float2bfloat16_rn(v.x - __bfloat162float(h0));
    __nv_bfloat16 l1 = __float2bfloat16_rn(v.y - __bfloat162float(h1));
    __nv_bfloat162 hp; hp.x = h0; hp.y = h1;
    __nv_bfloat162 lp; lp.x = l0; lp.y = l1;
    dhi[row * 32 + lane] = hp;
    dlo[row * 32 + lane] = lp;
    float s = v.x * v.x + v.y * v.y;
#pragma unroll
    for (int o = 16; o; o >>= 1) s += __shfl_xor_sync(0xffffffffu, s, o);
    if (lane == 0) {
        if (gw < B_ROWS) g_xn[row] = s;
        else { g_cn[row] = s; g_iv[row] = __expf(-2.0f * ls[row]); }
    }
}

// ---- warp-specialized pipelined main ----
__global__ void __launch_bounds__(THREADS, 1)
rbf_pipe(float* __restrict__ out) {
    extern __shared__ char smem[];
    const uint32_t sb = s2u(smem);
    const int tid = threadIdx.x;
    const int cta = blockIdx.x;

    const int u0 = (cta * NUNITS) / NCTA;
    const int u1 = ((cta + 1) * NUNITS) / NCTA;

    if (tid == 0) {
#pragma unroll
        for (int s = 0; s < NSTAGE; s++) {
            bar_init(sb + BAR + s * 8, 64);        // full: 64 producer threads
            bar_init(sb + BAR + 32 + s * 8, 256);  // empty: 256 consumer threads
        }
        bar_init(sb + BAR + 64, 64);               // a_full
        bar_init(sb + BAR + 72, 256);              // a_empty
    }
    __syncthreads();   // barrier init visible; only block-wide sync in kernel

    if (tid >= 256) {
        // ================= PRODUCER (2 warps) =================
        const int pt = tid - 256;                  // 0..63
        int ip = 0, bmi = -1;
        for (int t = u0; t < u1; ++t, ++ip) {
            const int nbm = t >> 5;
            if (nbm != bmi) {
                if (bmi >= 0) bar_wait(sb + BAR + 72, 0);   // consumers done w/ old A
                const int bm = nbm * BM;
#pragma unroll
                for (int i = 0; i < 32; i++) {
                    int l = pt + i * 64;
                    int half = l >> 10, li = l & 1023;
                    int row = li >> 3, q = li & 7;
                    uint32_t dst = sb + (half ? SA_LO : SA_HI) + row * 128 +
                                   ((q ^ (row & 7)) << 4);
                    const __nv_bfloat16* src =
                        (half ? g_xlo : g_xhi) + (size_t)(bm + row) * IN_DIM + q * 8;
                    cp16(dst, src);
                }
                if (pt < 32) cp16(sb + S_XN + pt * 16, g_xn + bm + pt * 4);
                CPCOMMIT(); CPWAIT0();
                bar_arrive(sb + BAR + 64);                   // a_full
                bmi = nbm;
            }
            const int s = ip & 3, f = ip >> 2;
            bar_wait(sb + BAR + 32 + s * 8, 1u ^ (f & 1));   // empty[s]
            const int bn = (t & 31) * BN;
            const uint32_t base = sb + ST_BASE + s * ST_SZ;
#pragma unroll
            for (int i = 0; i < 32; i++) {
                int l = pt + i * 64;
                int half = l >> 10, li = l & 1023;
                int row = li >> 3, q = li & 7;
                uint32_t dst = base + half * 16384 + row * 128 + ((q ^ (row & 7)) << 4);
                const __nv_bfloat16* src =
                    (half ? g_clo : g_chi) + (size_t)(bn + row) * IN_DIM + q * 8;
                cp16(dst, src);
            }
            if (pt < 32) cp16(base + ST_CN + pt * 16, g_cn + bn + pt * 4);
            else         cp16(base + ST_IV + (pt - 32) * 16, g_iv + bn + (pt - 32) * 4);
            CPCOMMIT(); CPWAIT0();
            bar_arrive(sb + BAR + s * 8);                    // full[s]
        }
        return;
    }

    // ================= CONSUMER (8 warps) =================
    const int wid = tid >> 5, lane = tid & 31;
    const int wm = wid >> 2, wn = wid & 3;    // 2x4 grid, 64x32 warp tiles
    const int lrow = lane & 15;
    const int ksel = lane >> 4;
    const int szk = lrow & 7;
    const int qr = lane >> 2;
    const int qc = (lane & 3) * 2;
    const float L2E = 1.4426950408889634f;

    uint32_t aBase[4];
#pragma unroll
    for (int t = 0; t < 4; t++)
        aBase[t] = sb + SA_HI + (wm * 64 + t * 16 + lrow) * 128;
    uint32_t rowB[2];
#pragma unroll
    for (int t = 0; t < 2; t++)
        rowB[t] = (wn * 32 + t * 16 + lrow) * 128;

    int bmi = u0 >> 5;
    bar_wait(sb + BAR + 64, 0);               // first A ready

    int ic = 0;
    for (int t = u0; t < u1; ++t, ++ic) {
        const int nbm = t >> 5;
        if (nbm != bmi) {                     // at most once per CTA
            bar_wait(sb + BAR + 64, 1);
            bmi = nbm;
        }
        const int s = ic & 3;
        bar_wait(sb + BAR + s * 8, (ic >> 2) & 1);   // full[s]

        const uint32_t stb = sb + ST_BASE + s * ST_SZ;
        uint32_t bBase[2];
        bBase[0] = stb + rowB[0];
        bBase[1] = stb + rowB[1];

        float acc[4][4][4];
#pragma unroll
        for (int i = 0; i < 4; i++)
#pragma unroll
            for (int j = 0; j < 4; j++)
#pragma unroll
                for (int k = 0; k < 4; k++) acc[i][j][k] = 0.f;

#pragma unroll
        for (int ks = 0; ks < 4; ks++) {
            const int kc = ks * 2 + ksel;
            const uint32_t ko = (uint32_t)((kc ^ szk) << 4);
            uint32_t Ah[4][4], Bh[2][4];
#pragma unroll
            for (int tt = 0; tt < 4; tt++) ldm_x4(Ah[tt], aBase[tt] + ko);
#pragma unroll
            for (int tt = 0; tt < 2; tt++) ldm_x4(Bh[tt], bBase[tt] + ko);
#pragma unroll
            for (int mt = 0; mt < 4; mt++)
#pragma unroll
                for (int p = 0; p < 2; p++) {
                    mma16816(acc[mt][p * 2 + 0], Ah[mt], Bh[p][0], Bh[p][2]);
                    mma16816(acc[mt][p * 2 + 1], Ah[mt], Bh[p][1], Bh[p][3]);
                }
            {
                uint32_t Bl[2][4];
#pragma unroll
                for (int tt = 0; tt < 2; tt++) ldm_x4(Bl[tt], bBase[tt] + 16384 + ko);
#pragma unroll
                for (int mt = 0; mt < 4; mt++)
#pragma unroll
                    for (int p = 0; p < 2; p++) {
                        mma16816(acc[mt][p * 2 + 0], Ah[mt], Bl[p][0], Bl[p][2]);
                        mma16816(acc[mt][p * 2 + 1], Ah[mt], Bl[p][1], Bl[p][3]);
                    }
            }
            {
                uint32_t Al[4][4];
#pragma unroll
                for (int tt = 0; tt < 4; tt++) ldm_x4(Al[tt], aBase[tt] + 16384 + ko);
#pragma unroll
                for (int mt = 0; mt < 4; mt++)
#pragma unroll
                    for (int p = 0; p < 2; p++) {
                        mma16816(acc[mt][p * 2 + 0], Al[mt], Bh[p][0], Bh[p][2]);
                        mma16816(acc[mt][p * 2 + 1], Al[mt], Bh[p][1], Bh[p][3]);
                    }
            }
        }

        // epilogue constants from the stage (before releasing it)
        const float* cn_s = (const float*)(smem + ST_BASE + s * ST_SZ + ST_CN);
        const float* iv_s = (const float*)(smem + ST_BASE + s * ST_SZ + ST_IV);
        const float* xn_s = (const float*)(smem + S_XN);
        float cn_l[8], ivl_l[8], xn_l[8];
#pragma unroll
        for (int nt = 0; nt < 4; nt++) {
            int col = wn * 32 + nt * 8 + qc;
            cn_l[nt * 2 + 0] = cn_s[col];
            cn_l[nt * 2 + 1] = cn_s[col + 1];
            ivl_l[nt * 2 + 0] = iv_s[col] * L2E;
            ivl_l[nt * 2 + 1] = iv_s[col + 1] * L2E;
        }
#pragma unroll
        for (int mt = 0; mt < 4; mt++) {
            xn_l[mt * 2 + 0] = xn_s[wm * 64 + mt * 16 + qr];
            xn_l[mt * 2 + 1] = xn_s[wm * 64 + mt * 16 + qr + 8];
        }

        bar_arrive(sb + BAR + 32 + s * 8);             // empty[s]
        if (t + 1 < u1 && ((t + 1) >> 5) != bmi)
            bar_arrive(sb + BAR + 72);                 // a_empty (strip done)

        // epilogue: out = exp2(min((2*dot - xn - cn) * iv*log2e, 0))
        const int bm = bmi * BM;
        const int bn = (t & 31) * BN;
#pragma unroll
        for (int mt = 0; mt < 4; mt++) {
            int r0 = wm * 64 + mt * 16 + qr;
            float xn0 = xn_l[mt * 2 + 0], xn1 = xn_l[mt * 2 + 1];
#pragma unroll
            for (int nt = 0; nt < 4; nt++) {
                int col = wn * 32 + nt * 8 + qc;
                float cn0 = cn_l[nt * 2], cn1 = cn_l[nt * 2 + 1];
                float iv0 = ivl_l[nt * 2], iv1 = ivl_l[nt * 2 + 1];
                const float* a = acc[mt][nt];
                float2 v0, v1;
                v0.x = ex2a(fminf(fmaf(2.f, a[0], -(xn0 + cn0)) * iv0, 0.f));
                v0.y = ex2a(fminf(fmaf(2.f, a[1], -(xn0 + cn1)) * iv1, 0.f));
                v1.x = ex2a(fminf(fmaf(2.f, a[2], -(xn1 + cn0)) * iv0, 0.f));
                v1.y = ex2a(fminf(fmaf(2.f, a[3], -(xn1 + cn1)) * iv1, 0.f));
                *(float2*)(out + (size_t)(bm + r0) * OUT_DIM + bn + col) = v0;
                *(float2*)(out + (size_t)(bm + r0 + 8) * OUT_DIM + bn + col) = v1;
            }
        }
    }
}

extern "C" void kernel_launch(void* const* d_in, const int* in_sizes, int n_in,
                              void* d_out, int out_size) {
    const float* x  = (const float*)d_in[0];
    const float* c  = (const float*)d_in[1];
    const float* ls = (const float*)d_in[2];
    float* out = (float*)d_out;
    (void)in_sizes; (void)n_in; (void)out_size;

    cudaFuncSetAttribute(rbf_pipe, cudaFuncAttributeMaxDynamicSharedMemorySize, SMEM_TOTAL);

    prep_all<<<(B_ROWS + OUT_DIM) / 8, 256>>>(x, c, ls);
    rbf_pipe<<<NCTA, THREADS, SMEM_TOTAL>>>(out);
}

// round 10
// speedup vs baseline: 1.6500x; 1.3600x over previous
#include <cuda_runtime.h>
#include <cuda_fp16.h>
#include <cstdint>

#define B_ROWS 16384
#define IN_DIM 64
#define OUT_DIM 4096
#define BM 128
#define BN 128

// ---- device-global scratch (alloc-guard-safe) ----
__device__ __half g_xh[B_ROWS * IN_DIM];
__device__ __half g_ch[OUT_DIM * IN_DIM];
__device__ float g_xn[B_ROWS];
__device__ float g_cn[OUT_DIM];
__device__ float g_iv[OUT_DIM];

// ---- smem layout (bytes) ----
#define SA    0            // 16KB (128 rows x 128B)
#define SB    16384        // 16KB
#define S_XN  32768        // 512B
#define S_CN  33280
#define S_IV  33792
#define SMEM_TOTAL 34304

__device__ __forceinline__ uint32_t s2u(const void* p) {
    uint32_t a;
    asm("{ .reg .u64 t; cvta.to.shared.u64 t, %1; cvt.u32.u64 %0, t; }" : "=r"(a) : "l"(p));
    return a;
}
__device__ __forceinline__ void ldm_x4(uint32_t* r, uint32_t addr) {
    asm volatile("ldmatrix.sync.aligned.m8n8.x4.shared.b16 {%0,%1,%2,%3}, [%4];"
                 : "=r"(r[0]), "=r"(r[1]), "=r"(r[2]), "=r"(r[3]) : "r"(addr));
}
__device__ __forceinline__ void mma16816(float* c, const uint32_t* a,
                                         uint32_t b0, uint32_t b1) {
    asm volatile(
        "mma.sync.aligned.m16n8k16.row.col.f32.f16.f16.f32 "
        "{%0,%1,%2,%3}, {%4,%5,%6,%7}, {%8,%9}, {%0,%1,%2,%3};"
        : "+f"(c[0]), "+f"(c[1]), "+f"(c[2]), "+f"(c[3])
        : "r"(a[0]), "r"(a[1]), "r"(a[2]), "r"(a[3]), "r"(b0), "r"(b1));
}
__device__ __forceinline__ float ex2a(float x) {
    float r;
    asm("ex2.approx.f32 %0, %1;" : "=f"(r) : "f"(x));
    return r;
}

// ---- prep (fused): f32 -> fp16, row norms, inv_sigma2 ----
__global__ void prep_all(const float* __restrict__ x, const float* __restrict__ c,
                         const float* __restrict__ ls) {
    int gw = (blockIdx.x * blockDim.x + threadIdx.x) >> 5;
    int lane = threadIdx.x & 31;
    const float* src;
    __half2* dst;
    int row;
    if (gw < B_ROWS) {
        row = gw; src = x; dst = (__half2*)g_xh;
    } else {
        row = gw - B_ROWS;
        if (row >= OUT_DIM) return;
        src = c; dst = (__half2*)g_ch;
    }
    float2 v = ((const float2*)src)[row * 32 + lane];
    dst[row * 32 + lane] = __floats2half2_rn(v.x, v.y);
    float s = v.x * v.x + v.y * v.y;
#pragma unroll
    for (int o = 16; o; o >>= 1) s += __shfl_xor_sync(0xffffffffu, s, o);
    if (lane == 0) {
        if (gw < B_ROWS) g_xn[row] = s;
        else { g_cn[row] = s; g_iv[row] = __expf(-2.0f * ls[row]); }
    }
}

// ---- main: 128x128 tile, 256 thr, 2 CTA/SM, single fp16 mma.sync ----
__global__ void __launch_bounds__(256, 2)
rbf_mma(float* __restrict__ out) {
    extern __shared__ char smem[];
    const uint32_t sb = s2u(smem);
    const int tid = threadIdx.x;
    const int bn = blockIdx.x * BN;
    const int bm = blockIdx.y * BM;

    // ---- global -> smem, XOR-swizzled (16B chunk q -> q ^ (row&7)) ----
    {
        const uint4* ax = (const uint4*)(g_xh + (size_t)bm * IN_DIM);
        const uint4* bc = (const uint4*)(g_ch + (size_t)bn * IN_DIM);
#pragma unroll
        for (int l = tid; l < 1024; l += 256) {
            int row = l >> 3, q = l & 7;
            int off = row * 128 + ((q ^ (row & 7)) << 4);
            *(uint4*)(smem + SA + off) = ax[l];
            *(uint4*)(smem + SB + off) = bc[l];
        }
        if (tid < 128) {
            ((float*)(smem + S_XN))[tid] = g_xn[bm + tid];
            ((float*)(smem + S_CN))[tid] = g_cn[bn + tid];
            ((float*)(smem + S_IV))[tid] = g_iv[bn + tid];
        }
    }
    __syncthreads();

    const int wid = tid >> 5, lane = tid & 31;
    const int wm = wid >> 2, wn = wid & 3;   // 2x4 warp grid, 64x32 warp tiles
    const int lrow = lane & 15;
    const int ksel = lane >> 4;              // lanes 16-31 take the odd 16B chunk
    const int szk = lrow & 7;

    uint32_t aBase[4], bBase[2];
#pragma unroll
    for (int t = 0; t < 4; t++)
        aBase[t] = sb + SA + (wm * 64 + t * 16 + lrow) * 128;
#pragma unroll
    for (int t = 0; t < 2; t++)
        bBase[t] = sb + SB + (wn * 32 + t * 16 + lrow) * 128;

    float acc[4][4][4];
#pragma unroll
    for (int i = 0; i < 4; i++)
#pragma unroll
        for (int j = 0; j < 4; j++)
#pragma unroll
            for (int k = 0; k < 4; k++) acc[i][j][k] = 0.f;

#pragma unroll
    for (int ks = 0; ks < 4; ks++) {
        const int kc = ks * 2 + ksel;        // 16B-chunk index along K
        const uint32_t ko = (uint32_t)((kc ^ szk) << 4);
        uint32_t Ah[4][4], Bh[2][4];
#pragma unroll
        for (int t = 0; t < 4; t++) ldm_x4(Ah[t], aBase[t] + ko);
#pragma unroll
        for (int t = 0; t < 2; t++) ldm_x4(Bh[t], bBase[t] + ko);
#pragma unroll
        for (int mt = 0; mt < 4; mt++)
#pragma unroll
            for (int p = 0; p < 2; p++) {
                mma16816(acc[mt][p * 2 + 0], Ah[mt], Bh[p][0], Bh[p][2]);
                mma16816(acc[mt][p * 2 + 1], Ah[mt], Bh[p][1], Bh[p][3]);
            }
    }

    // ---- epilogue: out = exp2(min((2*dot - xn - cn) * iv*log2e, 0)) ----
    const float* xn_s = (const float*)(smem + S_XN);
    const float* cn_s = (const float*)(smem + S_CN);
    const float* iv_s = (const float*)(smem + S_IV);
    const int qr = lane >> 2;
    const int qc = (lane & 3) * 2;
    const float L2E = 1.4426950408889634f;

    float cn_l[8], ivl_l[8], xn_l[8];
#pragma unroll
    for (int nt = 0; nt < 4; nt++) {
        int col = wn * 32 + nt * 8 + qc;
        cn_l[nt * 2 + 0] = cn_s[col];
        cn_l[nt * 2 + 1] = cn_s[col + 1];
        ivl_l[nt * 2 + 0] = iv_s[col] * L2E;
        ivl_l[nt * 2 + 1] = iv_s[col + 1] * L2E;
    }
#pragma unroll
    for (int mt = 0; mt < 4; mt++) {
        xn_l[mt * 2 + 0] = xn_s[wm * 64 + mt * 16 + qr];
        xn_l[mt * 2 + 1] = xn_s[wm * 64 + mt * 16 + qr + 8];
    }

#pragma unroll
    for (int mt = 0; mt < 4; mt++) {
        int r0 = wm * 64 + mt * 16 + qr;
        float xn0 = xn_l[mt * 2 + 0], xn1 = xn_l[mt * 2 + 1];
#pragma unroll
        for (int nt = 0; nt < 4; nt++) {
            int col = wn * 32 + nt * 8 + qc;
            float cn0 = cn_l[nt * 2], cn1 = cn_l[nt * 2 + 1];
            float iv0 = ivl_l[nt * 2], iv1 = ivl_l[nt * 2 + 1];
            const float* a = acc[mt][nt];
            float2 v0, v1;
            v0.x = ex2a(fminf(fmaf(2.f, a[0], -(xn0 + cn0)) * iv0, 0.f));
            v0.y = ex2a(fminf(fmaf(2.f, a[1], -(xn0 + cn1)) * iv1, 0.f));
            v1.x = ex2a(fminf(fmaf(2.f, a[2], -(xn1 + cn0)) * iv0, 0.f));
            v1.y = ex2a(fminf(fmaf(2.f, a[3], -(xn1 + cn1)) * iv1, 0.f));
            *(float2*)(out + (size_t)(bm + r0) * OUT_DIM + bn + col) = v0;
            *(float2*)(out + (size_t)(bm + r0 + 8) * OUT_DIM + bn + col) = v1;
        }
    }
}

extern "C" void kernel_launch(void* const* d_in, const int* in_sizes, int n_in,
                              void* d_out, int out_size) {
    const float* x  = (const float*)d_in[0];
    const float* c  = (const float*)d_in[1];
    const float* ls = (const float*)d_in[2];
    float* out = (float*)d_out;
    (void)in_sizes; (void)n_in; (void)out_size;

    cudaFuncSetAttribute(rbf_mma, cudaFuncAttributeMaxDynamicSharedMemorySize, SMEM_TOTAL);

    prep_all<<<(B_ROWS + OUT_DIM) / 8, 256>>>(x, c, ls);

    dim3 grid(OUT_DIM / BN, B_ROWS / BM);
    rbf_mma<<<grid, 256, SMEM_TOTAL>>>(out);
}

// round 11
// speedup vs baseline: 1.7576x; 1.0652x over previous
#include <cuda_runtime.h>
#include <cuda_fp16.h>
#include <cstdint>

#define B_ROWS 16384
#define IN_DIM 64
#define OUT_DIM 4096
#define BM 128
#define BN 128

// ---- device-global scratch (alloc-guard-safe) ----
__device__ __half g_xh[B_ROWS * IN_DIM];
__device__ __half g_ch[OUT_DIM * IN_DIM];
__device__ float g_xn[B_ROWS];
__device__ float g_cn[OUT_DIM];
__device__ float g_iv[OUT_DIM];

// ---- smem layout (bytes) ----
#define SA      0            // 16KB (128 rows x 128B)
#define SB      16384        // 16KB
#define S_XN    32768        // 512B
#define S_CN    33280
#define S_IV    33792
#define S_STAGE 34304        // 8 warps x 1KB warp-private stage
#define SMEM_TOTAL (34304 + 8192)

__device__ __forceinline__ uint32_t s2u(const void* p) {
    uint32_t a;
    asm("{ .reg .u64 t; cvta.to.shared.u64 t, %1; cvt.u32.u64 %0, t; }" : "=r"(a) : "l"(p));
    return a;
}
__device__ __forceinline__ void ldm_x4(uint32_t* r, uint32_t addr) {
    asm volatile("ldmatrix.sync.aligned.m8n8.x4.shared.b16 {%0,%1,%2,%3}, [%4];"
                 : "=r"(r[0]), "=r"(r[1]), "=r"(r[2]), "=r"(r[3]) : "r"(addr));
}
__device__ __forceinline__ void stm_x4(uint32_t addr, const uint32_t* r) {
    asm volatile("stmatrix.sync.aligned.m8n8.x4.shared.b16 [%0], {%1,%2,%3,%4};"
                 :: "r"(addr), "r"(r[0]), "r"(r[1]), "r"(r[2]), "r"(r[3]) : "memory");
}
__device__ __forceinline__ void mma16816(float* c, const uint32_t* a,
                                         uint32_t b0, uint32_t b1) {
    asm volatile(
        "mma.sync.aligned.m16n8k16.row.col.f32.f16.f16.f32 "
        "{%0,%1,%2,%3}, {%4,%5,%6,%7}, {%8,%9}, {%0,%1,%2,%3};"
        : "+f"(c[0]), "+f"(c[1]), "+f"(c[2]), "+f"(c[3])
        : "r"(a[0]), "r"(a[1]), "r"(a[2]), "r"(a[3]), "r"(b0), "r"(b1));
}
__device__ __forceinline__ float ex2a(float x) {
    float r;
    asm("ex2.approx.f32 %0, %1;" : "=f"(r) : "f"(x));
    return r;
}
__device__ __forceinline__ uint32_t pack_h2(float a, float b) {
    __half2 h = __floats2half2_rn(a, b);
    return *reinterpret_cast<uint32_t*>(&h);
}

// ---- prep (fused): f32 -> fp16, row norms, inv_sigma2 ----
__global__ void prep_all(const float* __restrict__ x, const float* __restrict__ c,
                         const float* __restrict__ ls) {
    int gw = (blockIdx.x * blockDim.x + threadIdx.x) >> 5;
    int lane = threadIdx.x & 31;
    const float* src;
    __half2* dst;
    int row;
    if (gw < B_ROWS) {
        row = gw; src = x; dst = (__half2*)g_xh;
    } else {
        row = gw - B_ROWS;
        if (row >= OUT_DIM) return;
        src = c; dst = (__half2*)g_ch;
    }
    float2 v = ((const float2*)src)[row * 32 + lane];
    dst[row * 32 + lane] = __floats2half2_rn(v.x, v.y);
    float s = v.x * v.x + v.y * v.y;
#pragma unroll
    for (int o = 16; o; o >>= 1) s += __shfl_xor_sync(0xffffffffu, s, o);
    if (lane == 0) {
        if (gw < B_ROWS) g_xn[row] = s;
        else { g_cn[row] = s; g_iv[row] = __expf(-2.0f * ls[row]); }
    }
}

// ---- main: 128x128 tile, 2 CTA/SM, fp16 mma + stmatrix-staged epilogue ----
__global__ void __launch_bounds__(256, 2)
rbf_mma(float* __restrict__ out) {
    extern __shared__ char smem[];
    const uint32_t sb = s2u(smem);
    const int tid = threadIdx.x;
    const int bn = blockIdx.x * BN;
    const int bm = blockIdx.y * BM;

    // ---- global -> smem, XOR-swizzled (16B chunk q -> q ^ (row&7)) ----
    {
        const uint4* ax = (const uint4*)(g_xh + (size_t)bm * IN_DIM);
        const uint4* bc = (const uint4*)(g_ch + (size_t)bn * IN_DIM);
#pragma unroll
        for (int l = tid; l < 1024; l += 256) {
            int row = l >> 3, q = l & 7;
            int off = row * 128 + ((q ^ (row & 7)) << 4);
            *(uint4*)(smem + SA + off) = ax[l];
            *(uint4*)(smem + SB + off) = bc[l];
        }
        if (tid < 128) {
            ((float*)(smem + S_XN))[tid] = g_xn[bm + tid];
            ((float*)(smem + S_CN))[tid] = g_cn[bn + tid];
            ((float*)(smem + S_IV))[tid] = g_iv[bn + tid];
        }
    }
    __syncthreads();

    const int wid = tid >> 5, lane = tid & 31;
    const int wm = wid >> 2, wn = wid & 3;   // 2x4 warp grid, 64x32 warp tiles
    const int lrow = lane & 15;
    const int ksel = lane >> 4;
    const int szk = lrow & 7;

    uint32_t aBase[4], bBase[2];
#pragma unroll
    for (int t = 0; t < 4; t++)
        aBase[t] = sb + SA + (wm * 64 + t * 16 + lrow) * 128;
#pragma unroll
    for (int t = 0; t < 2; t++)
        bBase[t] = sb + SB + (wn * 32 + t * 16 + lrow) * 128;

    float acc[4][4][4];
#pragma unroll
    for (int i = 0; i < 4; i++)
#pragma unroll
        for (int j = 0; j < 4; j++)
#pragma unroll
            for (int k = 0; k < 4; k++) acc[i][j][k] = 0.f;

#pragma unroll
    for (int ks = 0; ks < 4; ks++) {
        const int kc = ks * 2 + ksel;
        const uint32_t ko = (uint32_t)((kc ^ szk) << 4);
        uint32_t Ah[4][4], Bh[2][4];
#pragma unroll
        for (int t = 0; t < 4; t++) ldm_x4(Ah[t], aBase[t] + ko);
#pragma unroll
        for (int t = 0; t < 2; t++) ldm_x4(Bh[t], bBase[t] + ko);
#pragma unroll
        for (int mt = 0; mt < 4; mt++)
#pragma unroll
            for (int p = 0; p < 2; p++) {
                mma16816(acc[mt][p * 2 + 0], Ah[mt], Bh[p][0], Bh[p][2]);
                mma16816(acc[mt][p * 2 + 1], Ah[mt], Bh[p][1], Bh[p][3]);
            }
    }

    // ---- epilogue: stmatrix-stage dots (f16), coalesced exp+store ----
    const float* xn_s = (const float*)(smem + S_XN);
    const float* cn_s = (const float*)(smem + S_CN);
    const float* iv_s = (const float*)(smem + S_IV);
    const float L2E = 1.4426950408889634f;

    const int c8 = lane & 7;            // readback col-chunk (4 cols)
    const int s4 = lane >> 3;           // readback row-within-group
    float cn4[4], ivl4[4];
#pragma unroll
    for (int j = 0; j < 4; j++) {
        int col = wn * 32 + c8 * 4 + j;
        cn4[j] = cn_s[col];
        ivl4[j] = iv_s[col] * L2E;
    }

    const uint32_t wstage = sb + S_STAGE + wid * 1024;
    const uint32_t stm_addr = wstage + (lane & 7) * 64 + (lane >> 3) * 16;
    const char* rstage = smem + S_STAGE + wid * 1024;

#pragma unroll
    for (int mt = 0; mt < 4; mt++) {
        uint32_t h0[4], h1[4];
#pragma unroll
        for (int nt = 0; nt < 4; nt++) {
            const float* a = acc[mt][nt];
            h0[nt] = pack_h2(a[0], a[1]);   // rows qr
            h1[nt] = pack_h2(a[2], a[3]);   // rows qr+8
        }
        stm_x4(stm_addr, h0);               // stage rows 0..7  (16 rows x 64B)
        stm_x4(stm_addr + 512, h1);         // stage rows 8..15
        __syncwarp();

#pragma unroll
        for (int k = 0; k < 4; k++) {
            int s = k * 4 + s4;             // stage row 0..15
            uint2 raw = *(const uint2*)(rstage + s * 64 + c8 * 8);
            __half2 p0 = *reinterpret_cast<__half2*>(&raw.x);
            __half2 p1 = *reinterpret_cast<__half2*>(&raw.y);
            float2 f0 = __half22float2(p0);
            float2 f1 = __half22float2(p1);
            int row = wm * 64 + mt * 16 + s;
            float xn = xn_s[row];
            float4 o;
            o.x = ex2a(fminf(fmaf(2.f, f0.x, -(xn + cn4[0])) * ivl4[0], 0.f));
            o.y = ex2a(fminf(fmaf(2.f, f0.y, -(xn + cn4[1])) * ivl4[1], 0.f));
            o.z = ex2a(fminf(fmaf(2.f, f1.x, -(xn + cn4[2])) * ivl4[2], 0.f));
            o.w = ex2a(fminf(fmaf(2.f, f1.y, -(xn + cn4[3])) * ivl4[3], 0.f));
            *(float4*)(out + (size_t)(bm + row) * OUT_DIM + bn + wn * 32 + c8 * 4) = o;
        }
        __syncwarp();
    }
}

extern "C" void kernel_launch(void* const* d_in, const int* in_sizes, int n_in,
                              void* d_out, int out_size) {
    const float* x  = (const float*)d_in[0];
    const float* c  = (const float*)d_in[1];
    const float* ls = (const float*)d_in[2];
    float* out = (float*)d_out;
    (void)in_sizes; (void)n_in; (void)out_size;

    cudaFuncSetAttribute(rbf_mma, cudaFuncAttributeMaxDynamicSharedMemorySize, SMEM_TOTAL);

    prep_all<<<(B_ROWS + OUT_DIM) / 8, 256>>>(x, c, ls);

    dim3 grid(OUT_DIM / BN, B_ROWS / BM);
    rbf_mma<<<grid, 256, SMEM_TOTAL>>>(out);
}

// round 12
// speedup vs baseline: 1.8775x; 1.0682x over previous
#include <cuda_runtime.h>
#include <cuda_fp16.h>
#include <cstdint>

#define B_ROWS 16384
#define IN_DIM 64
#define OUT_DIM 4096
#define BM 128
#define BN 256

// ---- device-global scratch (alloc-guard-safe) ----
__device__ __half g_xh[B_ROWS * IN_DIM];
__device__ __half g_ch[OUT_DIM * IN_DIM];
__device__ float g_xn[B_ROWS];
__device__ float g_cn[OUT_DIM];
__device__ float g_iv[OUT_DIM];

// ---- smem layout (bytes) ----
#define SA      0            // 16KB (128 rows x 128B)
#define SB      16384        // 32KB (256 rows x 128B)
#define S_XN    49152        // 512B
#define S_CN    49664        // 1KB (256 f32)
#define S_IV    50688        // 1KB
#define S_STAGE 51712        // 8 warps x 2KB
#define SMEM_TOTAL 68096

__device__ __forceinline__ uint32_t s2u(const void* p) {
    uint32_t a;
    asm("{ .reg .u64 t; cvta.to.shared.u64 t, %1; cvt.u32.u64 %0, t; }" : "=r"(a) : "l"(p));
    return a;
}
__device__ __forceinline__ void ldm_x4(uint32_t* r, uint32_t addr) {
    asm volatile("ldmatrix.sync.aligned.m8n8.x4.shared.b16 {%0,%1,%2,%3}, [%4];"
                 : "=r"(r[0]), "=r"(r[1]), "=r"(r[2]), "=r"(r[3]) : "r"(addr));
}
__device__ __forceinline__ void stm_x4(uint32_t addr, uint32_t r0, uint32_t r1,
                                       uint32_t r2, uint32_t r3) {
    asm volatile("stmatrix.sync.aligned.m8n8.x4.shared.b16 [%0], {%1,%2,%3,%4};"
                 :: "r"(addr), "r"(r0), "r"(r1), "r"(r2), "r"(r3) : "memory");
}
__device__ __forceinline__ void mma_h(uint32_t* c, const uint32_t* a,
                                      uint32_t b0, uint32_t b1) {
    asm volatile(
        "mma.sync.aligned.m16n8k16.row.col.f16.f16.f16.f16 "
        "{%0,%1}, {%2,%3,%4,%5}, {%6,%7}, {%0,%1};"
        : "+r"(c[0]), "+r"(c[1])
        : "r"(a[0]), "r"(a[1]), "r"(a[2]), "r"(a[3]), "r"(b0), "r"(b1));
}
__device__ __forceinline__ float ex2a(float x) {
    float r;
    asm("ex2.approx.f32 %0, %1;" : "=f"(r) : "f"(x));
    return r;
}

// ---- prep (fused): f32 -> fp16, row norms, inv_sigma2 ----
__global__ void prep_all(const float* __restrict__ x, const float* __restrict__ c,
                         const float* __restrict__ ls) {
    int gw = (blockIdx.x * blockDim.x + threadIdx.x) >> 5;
    int lane = threadIdx.x & 31;
    const float* src;
    __half2* dst;
    int row;
    if (gw < B_ROWS) {
        row = gw; src = x; dst = (__half2*)g_xh;
    } else {
        row = gw - B_ROWS;
        if (row >= OUT_DIM) return;
        src = c; dst = (__half2*)g_ch;
    }
    float2 v = ((const float2*)src)[row * 32 + lane];
    dst[row * 32 + lane] = __floats2half2_rn(v.x, v.y);
    float s = v.x * v.x + v.y * v.y;
#pragma unroll
    for (int o = 16; o; o >>= 1) s += __shfl_xor_sync(0xffffffffu, s, o);
    if (lane == 0) {
        if (gw < B_ROWS) g_xn[row] = s;
        else { g_cn[row] = s; g_iv[row] = __expf(-2.0f * ls[row]); }
    }
}

// ---- main: 128x256 tile, 64x64 warp tiles, f16-acc mma, swizzled stage ----
__global__ void __launch_bounds__(256, 2)
rbf_mma(float* __restrict__ out) {
    extern __shared__ char smem[];
    const uint32_t sb = s2u(smem);
    const int tid = threadIdx.x;
    const int bn = blockIdx.x * BN;
    const int bm = blockIdx.y * BM;

    // ---- global -> smem, XOR-swizzled (16B chunk q -> q ^ (row&7)) ----
    {
        const uint4* ax = (const uint4*)(g_xh + (size_t)bm * IN_DIM);
        const uint4* bc = (const uint4*)(g_ch + (size_t)bn * IN_DIM);
#pragma unroll
        for (int l = tid; l < 1024; l += 256) {
            int row = l >> 3, q = l & 7;
            *(uint4*)(smem + SA + row * 128 + ((q ^ (row & 7)) << 4)) = ax[l];
        }
#pragma unroll
        for (int l = tid; l < 2048; l += 256) {
            int row = l >> 3, q = l & 7;
            *(uint4*)(smem + SB + row * 128 + ((q ^ (row & 7)) << 4)) = bc[l];
        }
        if (tid < 128) ((float*)(smem + S_XN))[tid] = g_xn[bm + tid];
        ((float*)(smem + S_CN))[tid] = g_cn[bn + tid];
        ((float*)(smem + S_IV))[tid] = g_iv[bn + tid];
    }
    __syncthreads();

    const int wid = tid >> 5, lane = tid & 31;
    const int wm = wid >> 2, wn = wid & 3;   // 2x4 warp grid, 64x64 warp tiles
    const int lrow = lane & 15;
    const int ksel = lane >> 4;
    const int szk = lrow & 7;

    uint32_t aBase[4], bBase[4];
#pragma unroll
    for (int t = 0; t < 4; t++) {
        aBase[t] = sb + SA + (wm * 64 + t * 16 + lrow) * 128;
        bBase[t] = sb + SB + (wn * 64 + t * 16 + lrow) * 128;
    }

    uint32_t acc[4][8][2];                   // f16x2-packed accumulators
#pragma unroll
    for (int i = 0; i < 4; i++)
#pragma unroll
        for (int j = 0; j < 8; j++) { acc[i][j][0] = 0u; acc[i][j][1] = 0u; }

#pragma unroll
    for (int ks = 0; ks < 4; ks++) {
        const int kc = ks * 2 + ksel;
        const uint32_t ko = (uint32_t)((kc ^ szk) << 4);
        uint32_t Ah[4][4], Bh[4][4];
#pragma unroll
        for (int t = 0; t < 4; t++) ldm_x4(Ah[t], aBase[t] + ko);
#pragma unroll
        for (int t = 0; t < 4; t++) ldm_x4(Bh[t], bBase[t] + ko);
#pragma unroll
        for (int mt = 0; mt < 4; mt++)
#pragma unroll
            for (int p = 0; p < 4; p++) {
                mma_h(acc[mt][p * 2 + 0], Ah[mt], Bh[p][0], Bh[p][2]);
                mma_h(acc[mt][p * 2 + 1], Ah[mt], Bh[p][1], Bh[p][3]);
            }
    }

    // ---- epilogue: swizzled matrix-major stage, coalesced exp+store ----
    const float* xn_s = (const float*)(smem + S_XN);
    const float* cn_s = (const float*)(smem + S_CN);
    const float* iv_s = (const float*)(smem + S_IV);
    const float L2E = 1.4426950408889634f;

    const int prow = lane >> 3;          // 0..3
    const int pcol = lane & 7;           // matrix index / col-chunk
    float cn8[8], ivl8[8];
#pragma unroll
    for (int j = 0; j < 8; j++) {
        int col = wn * 64 + pcol * 8 + j;
        cn8[j] = cn_s[col];
        ivl8[j] = iv_s[col] * L2E;
    }

    const uint32_t wstage = sb + S_STAGE + wid * 2048;
    // stm per-lane addr for matrix group (g, qbase): m = qbase + (lane>>3)
    const int m_loc = lane >> 3;
    const int rr_s = lane & 7;

#pragma unroll
    for (int mt = 0; mt < 4; mt++) {
#pragma unroll
        for (int g = 0; g < 2; g++)
#pragma unroll
            for (int qb = 0; qb < 8; qb += 4) {
                int m = qb + m_loc;
                uint32_t a = wstage + (uint32_t)((g * 8 + m) * 128 +
                             (((rr_s + m) & 7) << 4));
                stm_x4(a, acc[mt][qb + 0][g], acc[mt][qb + 1][g],
                          acc[mt][qb + 2][g], acc[mt][qb + 3][g]);
            }
        __syncwarp();

#pragma unroll
        for (int k = 0; k < 4; k++) {
            int r = k * 4 + prow;            // 0..15
            int g = r >> 3, rr = r & 7;
            uint32_t a = wstage + (uint32_t)((g * 8 + pcol) * 128 +
                         (((rr + pcol) & 7) << 4));
            uint4 raw = *(const uint4*)(smem + (a - sb));
            float2 f0 = __half22float2(*reinterpret_cast<__half2*>(&raw.x));
            float2 f1 = __half22float2(*reinterpret_cast<__half2*>(&raw.y));
            float2 f2 = __half22float2(*reinterpret_cast<__half2*>(&raw.z));
            float2 f3 = __half22float2(*reinterpret_cast<__half2*>(&raw.w));
            int row = wm * 64 + mt * 16 + r;
            float xn = xn_s[row];
            float4 o0, o1;
            o0.x = ex2a(fminf(fmaf(2.f, f0.x, -(xn + cn8[0])) * ivl8[0], 0.f));
            o0.y = ex2a(fminf(fmaf(2.f, f0.y, -(xn + cn8[1])) * ivl8[1], 0.f));
            o0.z = ex2a(fminf(fmaf(2.f, f1.x, -(xn + cn8[2])) * ivl8[2], 0.f));
            o0.w = ex2a(fminf(fmaf(2.f, f1.y, -(xn + cn8[3])) * ivl8[3], 0.f));
            o1.x = ex2a(fminf(fmaf(2.f, f2.x, -(xn + cn8[4])) * ivl8[4], 0.f));
            o1.y = ex2a(fminf(fmaf(2.f, f2.y, -(xn + cn8[5])) * ivl8[5], 0.f));
            o1.z = ex2a(fminf(fmaf(2.f, f3.x, -(xn + cn8[6])) * ivl8[6], 0.f));
            o1.w = ex2a(fminf(fmaf(2.f, f3.y, -(xn + cn8[7])) * ivl8[7], 0.f));
            float* op = out + (size_t)(bm + row) * OUT_DIM + bn + wn * 64 + pcol * 8;
            *(float4*)(op) = o0;
            *(float4*)(op + 4) = o1;
        }
        __syncwarp();
    }
}

extern "C" void kernel_launch(void* const* d_in, const int* in_sizes, int n_in,
                              void* d_out, int out_size) {
    const float* x  = (const float*)d_in[0];
    const float* c  = (const float*)d_in[1];
    const float* ls = (const float*)d_in[2];
    float* out = (float*)d_out;
    (void)in_sizes; (void)n_in; (void)out_size;

    cudaFuncSetAttribute(rbf_mma, cudaFuncAttributeMaxDynamicSharedMemorySize, SMEM_TOTAL);

    prep_all<<<(B_ROWS + OUT_DIM) / 8, 256>>>(x, c, ls);

    dim3 grid(OUT_DIM / BN, B_ROWS / BM);
    rbf_mma<<<grid, 256, SMEM_TOTAL>>>(out);
}